// round 1
// baseline (speedup 1.0000x reference)
#include <cuda_runtime.h>
#include <cuda_bf16.h>
#include <math.h>

// ============================================================================
// NTM forward, decomposed:
//   1) repack head-projection weights into Wcat[512][176] (+ bcat)
//   2) GEMM A: Xproj = x @ W_in + b_in + b_read          (65536x512x512)
//   3) scan:  128 persistent CTAs (one per batch), t = 0..511 sequential,
//             all recurrent state in SMEM, W_read cached in SMEM
//   4) GEMM C: out = sigmoid(Hall @ W_out + b_out)       (65536x512x512)
// ============================================================================

#define BB   128
#define TT   512
#define HH   512
#define NS   128      // memory slots
#define MD   20       // slot width
#define RH   4        // read heads
#define JTOT 170      // 66 write-head outputs + 4*26 read-head outputs
#define JPAD 176
#define MEMS 21       // padded mem row stride (bank-conflict free)

// ---- scratch (device globals; no allocation allowed) ----
__device__ float g_Xproj[(size_t)BB * TT * HH];   // 134 MB
__device__ float g_Hall [(size_t)BB * TT * HH];   // 134 MB
__device__ float g_Wcat [HH * JPAD];
__device__ float g_bcat [JPAD];

// ---- small helpers ----
__device__ __forceinline__ float sigmoidf_(float x) { return 1.f / (1.f + expf(-x)); }
__device__ __forceinline__ float softplusf_(float x) {
    return x > 20.f ? x : log1pf(expf(x));
}
__device__ __forceinline__ float wsum(float v) {
    #pragma unroll
    for (int o = 16; o; o >>= 1) v += __shfl_xor_sync(0xffffffffu, v, o);
    return v;
}
__device__ __forceinline__ float wmax(float v) {
    #pragma unroll
    for (int o = 16; o; o >>= 1) v = fmaxf(v, __shfl_xor_sync(0xffffffffu, v, o));
    return v;
}

// ============================================================================
// repack: Wcat[h][j] (j<66: write head, 66..169: read heads), bcat[j]
// ============================================================================
__global__ void repack_kernel(const float* __restrict__ W_whead,
                              const float* __restrict__ W_rhead,
                              const float* __restrict__ b_whead,
                              const float* __restrict__ b_rhead) {
    int h = blockIdx.x, j = threadIdx.x;              // 512 blocks x 176 threads
    float v = 0.f;
    if (j < 66) v = W_whead[h * 66 + j];
    else if (j < JTOT) {
        int u = j - 66, r = u / 26, o = u % 26;
        v = W_rhead[((size_t)r * HH + h) * 26 + o];
    }
    g_Wcat[h * JPAD + j] = v;
    if (h == 0) {
        float bv = 0.f;
        if (j < 66) bv = b_whead[j];
        else if (j < JTOT) {
            int u = j - 66, r = u / 26, o = u % 26;
            bv = b_rhead[r * 26 + o];
        }
        g_bcat[j] = bv;
    }
}

// ============================================================================
// fp32 tiled GEMM: C[M][512] = act(A[M][512] @ W[512][512] + b1 (+ b2))
// tile 128x128, BK=16, 256 threads, 8x8 microtile
// mode 0: A = A_ext, C = g_Xproj, no activation (bias b1+b2)
// mode 1: A = g_Hall, C = C_ext, sigmoid (bias b1)
// ============================================================================
__global__ void __launch_bounds__(256) sgemm512(const float* __restrict__ A_ext,
                                                const float* __restrict__ W,
                                                const float* __restrict__ b1,
                                                const float* __restrict__ b2,
                                                float* __restrict__ C_ext,
                                                int mode) {
    const float* A = (mode == 0) ? A_ext : g_Hall;
    float* C       = (mode == 0) ? g_Xproj : C_ext;

    __shared__ float As[16][128];
    __shared__ float Bs[16][128];

    const int tid = threadIdx.x;
    const int tx = tid & 15, ty = tid >> 4;
    const size_t bm = (size_t)blockIdx.y * 128;
    const int bn = blockIdx.x * 128;

    const int lm  = tid >> 2;   // 0..63   (A row)
    const int lk4 = tid & 3;    // 0..3    (A k float4 group)
    const int lkb = tid >> 5;   // 0..7    (B k row)
    const int ln4 = tid & 31;   // 0..31   (B n float4 group)

    float acc[8][8];
    #pragma unroll
    for (int i = 0; i < 8; i++)
        #pragma unroll
        for (int j = 0; j < 8; j++) acc[i][j] = 0.f;

    for (int k0 = 0; k0 < 512; k0 += 16) {
        #pragma unroll
        for (int i = 0; i < 2; i++) {
            int m = lm + i * 64;
            float4 v = *(const float4*)&A[(bm + m) * 512 + k0 + lk4 * 4];
            As[lk4 * 4 + 0][m] = v.x; As[lk4 * 4 + 1][m] = v.y;
            As[lk4 * 4 + 2][m] = v.z; As[lk4 * 4 + 3][m] = v.w;
        }
        #pragma unroll
        for (int i = 0; i < 2; i++) {
            int k = lkb + i * 8;
            float4 v = *(const float4*)&W[(size_t)(k0 + k) * 512 + bn + ln4 * 4];
            *(float4*)&Bs[k][ln4 * 4] = v;
        }
        __syncthreads();
        #pragma unroll
        for (int k = 0; k < 16; k++) {
            float a[8], bb[8];
            *(float4*)&a[0]  = *(const float4*)&As[k][ty * 8];
            *(float4*)&a[4]  = *(const float4*)&As[k][ty * 8 + 4];
            *(float4*)&bb[0] = *(const float4*)&Bs[k][tx * 8];
            *(float4*)&bb[4] = *(const float4*)&Bs[k][tx * 8 + 4];
            #pragma unroll
            for (int i = 0; i < 8; i++)
                #pragma unroll
                for (int j = 0; j < 8; j++)
                    acc[i][j] = fmaf(a[i], bb[j], acc[i][j]);
        }
        __syncthreads();
    }

    #pragma unroll
    for (int j = 0; j < 8; j++) {
        int n = bn + tx * 8 + j;
        float bias = b1[n] + (b2 ? b2[n] : 0.f);
        #pragma unroll
        for (int i = 0; i < 8; i++) {
            float v = acc[i][j] + bias;
            if (mode == 1) v = sigmoidf_(v);
            C[(bm + ty * 8 + i) * 512 + n] = v;
        }
    }
}

// ============================================================================
// scan kernel: one CTA per batch element, 256 threads, 512 sequential steps
// ============================================================================
// SMEM layout (float offsets)
#define SM_WS   0        // 80*512 = 40960  (W_read cache)
#define SM_H    40960    // 512
#define SM_MEM  41472    // 128*21 = 2688
#define SM_NRM  44160    // 128
#define SM_WR   44288    // 512
#define SM_WW   44800    // 128
#define SM_HP   44928    // 176
#define SM_BC   45104    // 176
#define SM_KK   45280    // 100
#define SM_PRM  45380    // 40  (per head: beta,g,s0,s1,s2,gamma,kn,-)
#define SM_ERA  45420    // 20
#define SM_ADD  45440    // 20
#define SM_SCR  45460    // 512
#define SM_RV   45972    // 80
#define SM_RED  46052    // 12
#define SM_PART 46064    // 704 (16B aligned)
#define SM_TOTF 46768
#define SM_BYTES (SM_TOTF * 4)

__global__ void __launch_bounds__(256, 1) ntm_scan(const float* __restrict__ W_read) {
    extern __shared__ float sm[];
    const int tid  = threadIdx.x;
    const int lane = tid & 31;
    const int warp = tid >> 5;
    const int b    = blockIdx.x;

    float* Ws   = sm + SM_WS;
    float* sh   = sm + SM_H;
    float* mem  = sm + SM_MEM;
    float* nrm  = sm + SM_NRM;
    float* wr   = sm + SM_WR;
    float* ww   = sm + SM_WW;
    float* hp   = sm + SM_HP;
    float* bc   = sm + SM_BC;
    float* kk   = sm + SM_KK;
    float* prm  = sm + SM_PRM;
    float* era  = sm + SM_ERA;
    float* addv = sm + SM_ADD;
    float* scr  = sm + SM_SCR;
    float* rv   = sm + SM_RV;
    float* red  = sm + SM_RED;
    float* part = sm + SM_PART;

    // ---- init ----
    {
        const float4* src = (const float4*)W_read;
        float4* dst = (float4*)Ws;
        for (int i = tid; i < (80 * 512) / 4; i += 256) dst[i] = src[i];
    }
    for (int i = tid; i < 512; i += 256) sh[i] = 0.f;
    for (int i = tid; i < NS * MEMS; i += 256) mem[i] = 1e-6f;
    for (int i = tid; i < 512; i += 256) wr[i] = 1.f / 128.f;
    if (tid < 128) ww[tid] = 1.f / 128.f;
    if (tid < JPAD) bc[tid] = g_bcat[tid];
    __syncthreads();
    if (tid < 128) {
        float s2 = 0.f;
        const float* mr = mem + tid * MEMS;
        #pragma unroll
        for (int m = 0; m < MD; m++) s2 = fmaf(mr[m], mr[m], s2);
        nrm[tid] = sqrtf(s2);
    }
    __syncthreads();

    const int isp = tid / 44;      // phase-1 i-split (valid tid<176)
    const int cg  = tid % 44;      // phase-1 col group
    const size_t bT = (size_t)b * TT;

    for (int t = 0; t < TT; t++) {
        const size_t xo = (bT + t) * HH;
        // prefetch Xproj early (consumed ~2000 cycles later)
        float xp0 = g_Xproj[xo + tid];
        float xp1 = g_Xproj[xo + tid + 256];

        // ---- phase 1: hp[j] = bcat[j] + sum_i h[i] * Wcat[i][j] ----
        if (tid < JPAD) {
            float4 acc = make_float4(0.f, 0.f, 0.f, 0.f);
            const float4* wp4 = ((const float4*)g_Wcat) + (size_t)(isp * 128) * 44 + cg;
            const float* hb = sh + isp * 128;
            #pragma unroll 4
            for (int i = 0; i < 128; i++) {
                float hv = hb[i];
                float4 w = wp4[(size_t)i * 44];
                acc.x = fmaf(hv, w.x, acc.x); acc.y = fmaf(hv, w.y, acc.y);
                acc.z = fmaf(hv, w.z, acc.z); acc.w = fmaf(hv, w.w, acc.w);
            }
            ((float4*)part)[isp * 44 + cg] = acc;
        }
        __syncthreads();
        if (tid < JPAD)
            hp[tid] = bc[tid] + part[tid] + part[176 + tid] + part[352 + tid] + part[528 + tid];
        __syncthreads();

        // ---- head parameter extraction ----
        if (tid < 100) {
            int hd = tid / 20, m = tid % 20;
            int j = (hd == 0) ? m : 66 + (hd - 1) * 26 + m;
            kk[hd * 20 + m] = tanhf(hp[j]);
        } else if (tid < 130) {
            int u = tid - 100, hd = u / 6, p = u % 6;
            int base = (hd == 0) ? 20 : 66 + (hd - 1) * 26 + 20;
            float v;
            if (p == 0)      v = softplusf_(hp[base]);
            else if (p == 1) v = sigmoidf_(hp[base + 1]);
            else if (p < 5) {
                float a0 = hp[base + 2], a1 = hp[base + 3], a2 = hp[base + 4];
                float mx = fmaxf(a0, fmaxf(a1, a2));
                float e0 = expf(a0 - mx), e1 = expf(a1 - mx), e2 = expf(a2 - mx);
                float den = e0 + e1 + e2;
                v = ((p == 2) ? e0 : (p == 3) ? e1 : e2) / den;
            } else           v = 1.f + softplusf_(hp[base + 5]);
            prm[hd * 8 + p] = v;
        } else if (tid < 150) {
            era[tid - 130] = sigmoidf_(hp[26 + (tid - 130)]);
        } else if (tid < 170) {
            addv[tid - 150] = tanhf(hp[46 + (tid - 150)]);
        } else if (tid < 175) {
            int hd = tid - 170;
            int jb = (hd == 0) ? 0 : 66 + (hd - 1) * 26;
            float s2 = 0.f;
            #pragma unroll
            for (int m = 0; m < 20; m++) {
                float kv = tanhf(hp[jb + m]);
                s2 = fmaf(kv, kv, s2);
            }
            prm[hd * 8 + 6] = sqrtf(s2);   // ||k||
        }
        __syncthreads();

        // ---- write-head addressing (old mem, old norms) ----
        {
            float a = -INFINITY;
            if (tid < 128) {
                float dot = 0.f;
                const float* mr = mem + tid * MEMS;
                #pragma unroll
                for (int m = 0; m < MD; m++) dot = fmaf(mr[m], kk[m], dot);
                a = prm[0] * dot / (nrm[tid] * prm[6] + 1e-8f);
            }
            float v = wmax(a);
            if (lane == 0) red[warp] = v;
            __syncthreads();
            float amax = red[0];
            #pragma unroll
            for (int i = 1; i < 8; i++) amax = fmaxf(amax, red[i]);
            __syncthreads();

            float e = (tid < 128) ? expf(a - amax) : 0.f;
            v = wsum(e);
            if (lane == 0) red[warp] = v;
            __syncthreads();
            float esum = red[0] + red[1] + red[2] + red[3] + red[4] + red[5] + red[6] + red[7];
            __syncthreads();

            if (tid < 128) {
                float wc = e / esum;
                float wg = prm[1] * wc + (1.f - prm[1]) * ww[tid];
                scr[tid] = wg;
            }
            __syncthreads();

            float wp_ = 0.f;
            if (tid < 128) {
                float ws_ = prm[2] * scr[(tid + 1) & 127] + prm[3] * scr[tid]
                          + prm[4] * scr[(tid - 1) & 127];
                wp_ = powf(ws_, prm[5]);
            }
            v = wsum(wp_);
            if (lane == 0) red[warp] = v;
            __syncthreads();
            float psum = red[0] + red[1] + red[2] + red[3] + red[4] + red[5] + red[6] + red[7];
            __syncthreads();
            if (tid < 128) ww[tid] = wp_ / (psum + 1e-8f);
        }
        __syncthreads();

        // ---- memory update ----
        for (int idx = tid; idx < NS * MD; idx += 256) {
            int n = idx / MD, m = idx - n * MD;
            float wv = ww[n];
            float* p = mem + n * MEMS + m;
            *p = (*p) * (1.f - wv * era[m]) + wv * addv[m];
        }
        __syncthreads();
        if (tid < 128) {
            float s2 = 0.f;
            const float* mr = mem + tid * MEMS;
            #pragma unroll
            for (int m = 0; m < MD; m++) s2 = fmaf(mr[m], mr[m], s2);
            nrm[tid] = sqrtf(s2);
        }
        __syncthreads();

        // ---- 4 read heads in parallel (64 threads each) on NEW mem ----
        {
            const int hd = tid >> 6;           // 0..3 -> head 1..4
            const int l  = tid & 63;
            const float* P = prm + (hd + 1) * 8;
            const float* K = kk + (hd + 1) * 20;
            const float beta = P[0], g = P[1], s0 = P[2], s1 = P[3], s2p = P[4],
                        gam = P[5], kn = P[6];
            const int n0 = l, n1 = l + 64;
            float dot0 = 0.f, dot1 = 0.f;
            const float* m0 = mem + n0 * MEMS;
            const float* m1 = mem + n1 * MEMS;
            #pragma unroll
            for (int m = 0; m < MD; m++) {
                dot0 = fmaf(m0[m], K[m], dot0);
                dot1 = fmaf(m1[m], K[m], dot1);
            }
            float a0 = beta * dot0 / (nrm[n0] * kn + 1e-8f);
            float a1 = beta * dot1 / (nrm[n1] * kn + 1e-8f);

            float v = wmax(fmaxf(a0, a1));
            if (lane == 0) red[warp] = v;
            __syncthreads();
            float amax = fmaxf(red[2 * hd], red[2 * hd + 1]);
            __syncthreads();

            float e0 = expf(a0 - amax), e1 = expf(a1 - amax);
            v = wsum(e0 + e1);
            if (lane == 0) red[warp] = v;
            __syncthreads();
            float esum = red[2 * hd] + red[2 * hd + 1];
            __syncthreads();

            float* wrh = wr + hd * 128;
            float wg0 = g * (e0 / esum) + (1.f - g) * wrh[n0];
            float wg1 = g * (e1 / esum) + (1.f - g) * wrh[n1];
            float* S = scr + hd * 128;
            S[n0] = wg0; S[n1] = wg1;
            __syncthreads();

            float ws0 = s0 * S[(n0 + 1) & 127] + s1 * S[n0] + s2p * S[(n0 - 1) & 127];
            float ws1 = s0 * S[(n1 + 1) & 127] + s1 * S[n1] + s2p * S[(n1 - 1) & 127];
            float p0 = powf(ws0, gam), p1 = powf(ws1, gam);
            v = wsum(p0 + p1);
            if (lane == 0) red[warp] = v;
            __syncthreads();
            float psum = red[2 * hd] + red[2 * hd + 1];
            __syncthreads();
            wrh[n0] = p0 / (psum + 1e-8f);
            wrh[n1] = p1 / (psum + 1e-8f);
        }
        __syncthreads();

        // ---- read vectors: rv[r*20+m] = sum_n w_r[r][n] * mem[n][m] ----
        if (tid < 80) {
            int r = tid / 20, m = tid - r * 20;
            const float* wrh = wr + r * 128;
            float acc = 0.f;
            #pragma unroll 4
            for (int n = 0; n < 128; n++)
                acc = fmaf(wrh[n], mem[n * MEMS + m], acc);
            rv[tid] = acc;
        }
        __syncthreads();

        // ---- h = relu(Xproj + r @ W_read), store to Hall ----
        {
            float acc0 = xp0, acc1 = xp1;
            #pragma unroll 8
            for (int k = 0; k < 80; k++) {
                float r_ = rv[k];
                acc0 = fmaf(r_, Ws[k * 512 + tid], acc0);
                acc1 = fmaf(r_, Ws[k * 512 + tid + 256], acc1);
            }
            float h0 = fmaxf(acc0, 0.f), h1 = fmaxf(acc1, 0.f);
            sh[tid] = h0; sh[tid + 256] = h1;
            g_Hall[xo + tid] = h0;
            g_Hall[xo + tid + 256] = h1;
        }
        __syncthreads();
    }
}

// ============================================================================
// launch
// ============================================================================
extern "C" void kernel_launch(void* const* d_in, const int* in_sizes, int n_in,
                              void* d_out, int out_size) {
    const float* x       = (const float*)d_in[0];
    const float* W_in    = (const float*)d_in[1];
    const float* b_in    = (const float*)d_in[2];
    const float* W_read  = (const float*)d_in[3];
    const float* b_read  = (const float*)d_in[4];
    const float* W_out   = (const float*)d_in[5];
    const float* b_out   = (const float*)d_in[6];
    const float* W_rhead = (const float*)d_in[7];
    const float* b_rhead = (const float*)d_in[8];
    const float* W_whead = (const float*)d_in[9];
    const float* b_whead = (const float*)d_in[10];
    float* out = (float*)d_out;

    cudaFuncSetAttribute(ntm_scan, cudaFuncAttributeMaxDynamicSharedMemorySize, SM_BYTES);

    // 1) repack head weights
    repack_kernel<<<HH, JPAD>>>(W_whead, W_rhead, b_whead, b_rhead);

    // 2) Xproj = x @ W_in + b_in + b_read
    sgemm512<<<dim3(4, 512), 256>>>(x, W_in, b_in, b_read, nullptr, 0);

    // 3) sequential scan (one CTA per batch element)
    ntm_scan<<<BB, 256, SM_BYTES>>>(W_read);

    // 4) out = sigmoid(Hall @ W_out + b_out)
    sgemm512<<<dim3(4, 512), 256>>>(nullptr, W_out, b_out, nullptr, out, 1);
}